// round 4
// baseline (speedup 1.0000x reference)
#include <cuda_runtime.h>
#include <math.h>

// Problem constants
#define CC 10000
#define KK 4
#define DD 2048
#define ROWS (CC * KK)                   // 40000
#define WARPS_PER_BLOCK 8
#define THREADS (WARPS_PER_BLOCK * 32)   // 256
#define GRID (ROWS / WARPS_PER_BLOCK)    // 5000 blocks, one (m,s) partial each

// Scratch (allocation-free rule -> device globals)
__device__ float g_pm[GRID];          // per-block max logit
__device__ float g_ps[GRID];          // per-block sum exp(logit - m)
__device__ float g_lbl[KK];           // d[label, k]
__device__ unsigned int g_ticket;     // completion counter (self-resetting)

__global__ __launch_bounds__(THREADS, 8) void fused_kernel(
    const float* __restrict__ feat,
    const int*  __restrict__ label,
    const float* __restrict__ protos,
    float* __restrict__ out)
{
    __shared__ float sf[DD];
    __shared__ float sd[WARPS_PER_BLOCK];
    __shared__ float sred[WARPS_PER_BLOCK];
    __shared__ float s_bcast;
    __shared__ int s_islast;

    // stage feature (8 KB) in smem with float4 loads
    {
        float4* sf4 = (float4*)sf;
        const float4* f4 = (const float4*)feat;
        #pragma unroll
        for (int i = threadIdx.x; i < DD / 4; i += THREADS)
            sf4[i] = f4[i];
    }
    __syncthreads();

    const int warp = threadIdx.x >> 5;
    const int lane = threadIdx.x & 31;
    const int row  = blockIdx.x * WARPS_PER_BLOCK + warp;

    const float4* __restrict__ p = (const float4*)(protos + (size_t)row * DD);
    const float4* __restrict__ f = (const float4*)sf;

    float acc = 0.0f;
    // D=2048 floats = 512 float4; warp covers 32 float4 per iter -> 16 iters
    #pragma unroll
    for (int it = 0; it < DD / 128; ++it) {
        float4 pv = __ldcs(&p[it * 32 + lane]);   // streaming: evict-first
        float4 fv = f[it * 32 + lane];
        float dx = pv.x - fv.x;
        float dy = pv.y - fv.y;
        float dz = pv.z - fv.z;
        float dw = pv.w - fv.w;
        acc = fmaf(dx, dx, acc);
        acc = fmaf(dy, dy, acc);
        acc = fmaf(dz, dz, acc);
        acc = fmaf(dw, dw, acc);
    }

    // warp reduction -> full squared distance for this row
    #pragma unroll
    for (int o = 16; o > 0; o >>= 1)
        acc += __shfl_xor_sync(0xffffffffu, acc, o);

    if (lane == 0) {
        sd[warp] = acc;
        if ((row >> 2) == *label)          // row / KK
            g_lbl[row & 3] = acc;          // row % KK
    }
    __syncthreads();

    // Warp 0 combines the 8 row distances into one (m, s) partial.
    if (warp == 0) {
        float l = (lane < WARPS_PER_BLOCK) ? -sd[lane] : -INFINITY;
        float m = l;
        #pragma unroll
        for (int o = 4; o > 0; o >>= 1)
            m = fmaxf(m, __shfl_xor_sync(0xffffffffu, m, o));
        float e = (lane < WARPS_PER_BLOCK) ? expf(l - m) : 0.0f;
        #pragma unroll
        for (int o = 4; o > 0; o >>= 1)
            e += __shfl_xor_sync(0xffffffffu, e, o);
        if (lane == 0) {
            g_pm[blockIdx.x] = m;
            g_ps[blockIdx.x] = e;
        }
    }

    // ---- last-block-done final reduction ----
    if (threadIdx.x == 0) {
        __threadfence();   // publish g_pm/g_ps/g_lbl before ticket
        unsigned int t = atomicAdd(&g_ticket, 1u);
        s_islast = (t == (unsigned int)(GRID - 1));
    }
    __syncthreads();
    if (!s_islast) return;
    __threadfence();       // acquire side: see all partials

    const int tid = threadIdx.x;

    // phase 1: global max over 5000 partials (~20 per thread, fmax chain only)
    float mloc = -INFINITY;
    for (int i = tid; i < GRID; i += THREADS)
        mloc = fmaxf(mloc, g_pm[i]);
    #pragma unroll
    for (int o = 16; o > 0; o >>= 1)
        mloc = fmaxf(mloc, __shfl_xor_sync(0xffffffffu, mloc, o));
    if (lane == 0) sred[warp] = mloc;
    __syncthreads();
    if (warp == 0) {
        float v = (lane < WARPS_PER_BLOCK) ? sred[lane] : -INFINITY;
        #pragma unroll
        for (int o = 4; o > 0; o >>= 1)
            v = fmaxf(v, __shfl_xor_sync(0xffffffffu, v, o));
        if (lane == 0) s_bcast = v;
    }
    __syncthreads();
    const float M = s_bcast;

    // phase 2: sum with independent exps (partials re-read from L2)
    float sloc = 0.0f;
    for (int i = tid; i < GRID; i += THREADS)
        sloc += g_ps[i] * expf(g_pm[i] - M);
    #pragma unroll
    for (int o = 16; o > 0; o >>= 1)
        sloc += __shfl_xor_sync(0xffffffffu, sloc, o);
    if (lane == 0) sred[warp] = sloc;
    __syncthreads();
    if (warp == 0) {
        float v = (lane < WARPS_PER_BLOCK) ? sred[lane] : 0.0f;
        #pragma unroll
        for (int o = 4; o > 0; o >>= 1)
            v += __shfl_xor_sync(0xffffffffu, v, o);
        if (lane == 0) {
            float log_one = M + logf(v);
            float lblsum = g_lbl[0] + g_lbl[1] + g_lbl[2] + g_lbl[3];
            // probability = sum_k (log_one - logits[label,k]) = K*log_one + sum_k d[label,k]
            out[0] = (float)KK * log_one + lblsum;
            g_ticket = 0u;   // reset for next graph replay
        }
    }
}

extern "C" void kernel_launch(void* const* d_in, const int* in_sizes, int n_in,
                              void* d_out, int out_size)
{
    const float* feat   = (const float*)d_in[0];
    const int*   label  = (const int*)d_in[1];
    const float* protos = (const float*)d_in[2];
    float* out = (float*)d_out;

    fused_kernel<<<GRID, THREADS>>>(feat, label, protos, out);
}

// round 5
// speedup vs baseline: 1.1382x; 1.1382x over previous
#include <cuda_runtime.h>
#include <math.h>

// Problem constants
#define CC 10000
#define KK 4
#define DD 2048
#define ROWS (CC * KK)                   // 40000
#define WARPS_PER_BLOCK 8
#define THREADS (WARPS_PER_BLOCK * 32)   // 256
#define GRID (ROWS / WARPS_PER_BLOCK)    // 5000 blocks, one (m,s) partial each

// Scratch (allocation-free rule -> device globals)
__device__ float g_pm[GRID];     // per-block max logit
__device__ float g_ps[GRID];     // per-block sum exp(logit - m)
__device__ float g_lbl[KK];      // d[label, k]

// Kernel 1: one warp per prototype row; per-block logsumexp partial.
// Exactly the R1/R2 streaming shape that measured 6.59 TB/s. No fences,
// no atomics, no cache hints in the hot loop.
__global__ __launch_bounds__(THREADS) void dist_kernel(
    const float* __restrict__ feat,
    const int*  __restrict__ label,
    const float* __restrict__ protos)
{
    __shared__ float sf[DD];
    __shared__ float sd[WARPS_PER_BLOCK];

    for (int i = threadIdx.x; i < DD; i += THREADS)
        sf[i] = feat[i];
    __syncthreads();

    const int warp = threadIdx.x >> 5;
    const int lane = threadIdx.x & 31;
    const int row  = blockIdx.x * WARPS_PER_BLOCK + warp;

    const float4* __restrict__ p = (const float4*)(protos + (size_t)row * DD);
    const float4* __restrict__ f = (const float4*)sf;

    float acc = 0.0f;
    // D=2048 floats = 512 float4; warp covers 32 float4 per iter -> 16 iters
    #pragma unroll
    for (int it = 0; it < DD / 128; ++it) {
        float4 pv = p[it * 32 + lane];
        float4 fv = f[it * 32 + lane];
        float dx = pv.x - fv.x;
        float dy = pv.y - fv.y;
        float dz = pv.z - fv.z;
        float dw = pv.w - fv.w;
        acc = fmaf(dx, dx, acc);
        acc = fmaf(dy, dy, acc);
        acc = fmaf(dz, dz, acc);
        acc = fmaf(dw, dw, acc);
    }

    // warp reduction -> full squared distance for this row
    #pragma unroll
    for (int o = 16; o > 0; o >>= 1)
        acc += __shfl_xor_sync(0xffffffffu, acc, o);

    if (lane == 0) {
        sd[warp] = acc;
        if ((row >> 2) == *label)          // row / KK
            g_lbl[row & 3] = acc;          // row % KK
    }
    __syncthreads();

    // Warp 0 combines the 8 row distances into one (m, s) partial.
    if (warp == 0) {
        float l = (lane < WARPS_PER_BLOCK) ? -sd[lane] : -INFINITY;
        float m = l;
        #pragma unroll
        for (int o = 4; o > 0; o >>= 1)
            m = fmaxf(m, __shfl_xor_sync(0xffffffffu, m, o));
        float e = (lane < WARPS_PER_BLOCK) ? expf(l - m) : 0.0f;
        #pragma unroll
        for (int o = 4; o > 0; o >>= 1)
            e += __shfl_xor_sync(0xffffffffu, e, o);
        if (lane == 0) {
            g_pm[blockIdx.x] = m;
            g_ps[blockIdx.x] = e;
        }
    }
}

// Kernel 2: two-phase reduce of 5000 (m,s) partials. No serial online-LSE
// chain: phase 1 is a pure fmax tree, phase 2 sums independent exps.
__global__ __launch_bounds__(1024) void reduce_kernel(float* __restrict__ out)
{
    __shared__ float sred[32];
    __shared__ float s_bcast;

    const int tid  = threadIdx.x;
    const int warp = tid >> 5;
    const int lane = tid & 31;

    // phase 0: load partials into registers (5 independent slots/thread)
    float m0 = -INFINITY, m1 = -INFINITY, m2 = -INFINITY, m3 = -INFINITY, m4 = -INFINITY;
    float s0 = 0.f, s1 = 0.f, s2 = 0.f, s3 = 0.f, s4 = 0.f;
    if (tid          < GRID) { m0 = g_pm[tid];          s0 = g_ps[tid]; }
    if (tid + 1024   < GRID) { m1 = g_pm[tid + 1024];   s1 = g_ps[tid + 1024]; }
    if (tid + 2048   < GRID) { m2 = g_pm[tid + 2048];   s2 = g_ps[tid + 2048]; }
    if (tid + 3072   < GRID) { m3 = g_pm[tid + 3072];   s3 = g_ps[tid + 3072]; }
    if (tid + 4096   < GRID) { m4 = g_pm[tid + 4096];   s4 = g_ps[tid + 4096]; }

    // phase 1: global max (fmax tree only)
    float mloc = fmaxf(fmaxf(fmaxf(m0, m1), fmaxf(m2, m3)), m4);
    #pragma unroll
    for (int o = 16; o > 0; o >>= 1)
        mloc = fmaxf(mloc, __shfl_xor_sync(0xffffffffu, mloc, o));
    if (lane == 0) sred[warp] = mloc;
    __syncthreads();
    if (warp == 0) {
        float v = sred[lane];
        #pragma unroll
        for (int o = 16; o > 0; o >>= 1)
            v = fmaxf(v, __shfl_xor_sync(0xffffffffu, v, o));
        if (lane == 0) s_bcast = v;
    }
    __syncthreads();
    const float M = s_bcast;

    // phase 2: independent exps (s=0 guards the -inf slots: 0 * exp(-inf) -> 0*0)
    float sloc = s0 * expf(m0 - M) + s1 * expf(m1 - M) + s2 * expf(m2 - M)
               + s3 * expf(m3 - M) + s4 * expf(m4 - M);
    #pragma unroll
    for (int o = 16; o > 0; o >>= 1)
        sloc += __shfl_xor_sync(0xffffffffu, sloc, o);
    if (lane == 0) sred[warp] = sloc;
    __syncthreads();
    if (warp == 0) {
        float v = sred[lane];
        #pragma unroll
        for (int o = 16; o > 0; o >>= 1)
            v += __shfl_xor_sync(0xffffffffu, v, o);
        if (lane == 0) {
            float log_one = M + logf(v);
            float lblsum = g_lbl[0] + g_lbl[1] + g_lbl[2] + g_lbl[3];
            // probability = sum_k (log_one - logits[label,k]) = K*log_one + sum_k d[label,k]
            out[0] = (float)KK * log_one + lblsum;
        }
    }
}

extern "C" void kernel_launch(void* const* d_in, const int* in_sizes, int n_in,
                              void* d_out, int out_size)
{
    const float* feat   = (const float*)d_in[0];
    const int*   label  = (const int*)d_in[1];
    const float* protos = (const float*)d_in[2];
    float* out = (float*)d_out;

    dist_kernel<<<GRID, THREADS>>>(feat, label, protos);
    reduce_kernel<<<1, 1024>>>(out);
}